// round 16
// baseline (speedup 1.0000x reference)
#include <cuda_runtime.h>

#define NB 32
#define NS 1024
#define NV 8

typedef unsigned long long ull;

// smem layout (floats), float4-aligned
#define O_EMB   0
#define O_LN1G  32
#define O_LN1B  40
#define O_WQKV  48
#define O_WO    144
#define O_LN2G  176
#define O_LN2B  184
#define O_W1    192
#define O_B1    320
#define O_B2    352
#define O_OUTW  360
#define O_W2T   392
#define O_SKV   520   // [l][state][head][k0,k1,v0,v1] = 2*8*2*4 floats
#define O_SLOG  648
#define S_TOTAL 712

__device__ __forceinline__ float ex2(float x) {
    float y; asm("ex2.approx.ftz.f32 %0, %1;" : "=f"(y) : "f"(x)); return y;
}
__device__ __forceinline__ float rcpa(float x) {
    float y; asm("rcp.approx.ftz.f32 %0, %1;" : "=f"(y) : "f"(x)); return y;
}
__device__ __forceinline__ float rsqa(float x) {
    float y; asm("rsqrt.approx.ftz.f32 %0, %1;" : "=f"(y) : "f"(x)); return y;
}
__device__ __forceinline__ float4 ld4(const float* p) { return *(const float4*)p; }

// Branch-free erf (Abramowitz-Stegun 7.1.26, |abs err| <= 1.5e-7).
__device__ __forceinline__ float erf_bf(float x) {
    float ax = fabsf(x);
    float t  = rcpa(fmaf(0.3275911f, ax, 1.0f));
    float p  = t * fmaf(t, fmaf(t, fmaf(t, fmaf(t, 1.061405429f, -1.453152027f),
                     1.421413741f), -0.284496736f), 0.254829592f);
    float e  = ex2(-1.4426950408889634f * ax * ax);
    return copysignf(fmaf(-p, e, 1.0f), x);
}

// ---------------------------------------------------------------------------
// ONE kernel, one block per batch (256 threads = 8 warps), ONE block barrier.
// Warp 0: loads all tokens, stages weights, warp-local histogram, runs the
// 2-layer network for the 8 distinct token states (vocab=8, no positional
// encoding => equal ids share state; attention = histogram-weighted 8-term
// sum); lanes = 8 states x 4 roles (role pairs split heads, FFN split 4 ways).
// Dependency chains minimized: batched attention LDS + pairwise-tree sums,
// per-head partial Wo before the recombine shfl, tree-form LN sums.
// Warps 1-7 just fetch their scatter tokens and wait at the single barrier.
// ---------------------------------------------------------------------------
__global__ void __launch_bounds__(256) fused_kernel(
    const int*   __restrict__ tok,
    const float* __restrict__ emb,
    const float* __restrict__ ln1_g, const float* __restrict__ ln1_b,
    const float* __restrict__ wqkv,  const float* __restrict__ wo,
    const float* __restrict__ ln2_g, const float* __restrict__ ln2_b,
    const float* __restrict__ w1,    const float* __restrict__ b1,
    const float* __restrict__ w2,    const float* __restrict__ b2,
    const float* __restrict__ out_w,
    float* __restrict__ out)
{
    __shared__ __align__(16) float sw[S_TOTAL];

    const int b    = blockIdx.x;
    const int t    = threadIdx.x;
    const int warp = t >> 5;
    const int lane = t & 31;

    const int4* tp = (const int4*)(tok + b * NS);
    int4 my;                                       // this thread's 4 scatter tokens

    if (warp == 0) {
        // ---- tokens: all 8 chunks (one round-trip, feeds histogram) ----
        int4 tk[8];
        #pragma unroll
        for (int k = 0; k < 8; k++) tk[k] = tp[lane + 32 * k];
        my = tk[0];

        // ---- weight staging: 98 float4 + 128 transposed-w2 scalars ----
        #pragma unroll
        for (int k = 0; k < 4; k++) {
            int idx = lane + 32 * k;
            if (idx < 98) {
                const float4* src;
                if      (idx < 8)  src = (const float4*)emb   + idx;
                else if (idx < 10) src = (const float4*)ln1_g + (idx - 8);
                else if (idx < 12) src = (const float4*)ln1_b + (idx - 10);
                else if (idx < 36) src = (const float4*)wqkv  + (idx - 12);
                else if (idx < 44) src = (const float4*)wo    + (idx - 36);
                else if (idx < 46) src = (const float4*)ln2_g + (idx - 44);
                else if (idx < 48) src = (const float4*)ln2_b + (idx - 46);
                else if (idx < 80) src = (const float4*)w1    + (idx - 48);
                else if (idx < 88) src = (const float4*)b1    + (idx - 80);
                else if (idx < 90) src = (const float4*)b2    + (idx - 88);
                else               src = (const float4*)out_w + (idx - 90);
                ((float4*)sw)[idx] = *src;
            }
            int i  = lane + 32 * k;                // w2t: [l][fl][e]
            int l  = i >> 6, fl = (i >> 2) & 15, e = i & 3;
            sw[O_W2T + i] = w2[l * 64 + e * 16 + fl];
        }

        // ---- warp-local histogram (byte fields -> 16-bit fields) ----
        ull c = 0;
        #pragma unroll
        for (int k = 0; k < 8; k++) {
            c += (1ull << (tk[k].x * 8)) + (1ull << (tk[k].y * 8))
               + (1ull << (tk[k].z * 8)) + (1ull << (tk[k].w * 8));
        }                                          // per-lane bins <= 32: no carry
        ull lo =  c       & 0x00FF00FF00FF00FFull; // ids 0,2,4,6
        ull hi = (c >> 8) & 0x00FF00FF00FF00FFull; // ids 1,3,5,7
        #pragma unroll
        for (int o = 16; o; o >>= 1) {
            lo += __shfl_xor_sync(0xffffffffu, lo, o);
            hi += __shfl_xor_sync(0xffffffffu, hi, o); // sums <= 1024: 16-bit ok
        }
        float cw[8];
        cw[0] = (float)( lo        & 0xFFFF); cw[1] = (float)( hi        & 0xFFFF);
        cw[2] = (float)((lo >> 16) & 0xFFFF); cw[3] = (float)((hi >> 16) & 0xFFFF);
        cw[4] = (float)((lo >> 32) & 0xFFFF); cw[5] = (float)((hi >> 32) & 0xFFFF);
        cw[6] = (float)((lo >> 48) & 0xFFFF); cw[7] = (float)( hi >> 48);

        __syncwarp();                              // staged weights visible

        // ---- network: lanes = 8 states x 4 roles; roles {0,1}=head0 {2,3}=head1
        const int s  = lane >> 2, r = lane & 3;
        const int hr = r >> 1;                     // this lane's head
        float4 ev = ld4(sw + O_EMB + s * 4);
        float x0 = ev.x, x1 = ev.y, x2 = ev.z, x3 = ev.w;
        const float SC = 0.70710678118654752f * 1.4426950408889634f;

        #pragma unroll
        for (int l = 0; l < 2; l++) {
            // LN1 (tree-form sums)
            float4 g1 = ld4(sw + O_LN1G + l*4), b1v = ld4(sw + O_LN1B + l*4);
            float mu = 0.25f * ((x0 + x1) + (x2 + x3));
            float d0 = x0-mu, d1 = x1-mu, d2 = x2-mu, d3 = x3-mu;
            float rr = rsqa(fmaf(0.25f, (d0*d0 + d1*d1) + (d2*d2 + d3*d3), 1e-5f));
            float h0 = d0*rr*g1.x+b1v.x, h1 = d1*rr*g1.y+b1v.y;
            float h2 = d2*rr*g1.z+b1v.z, h3 = d3*rr*g1.w+b1v.w;

            // K,V: 8 dots (all lanes); q: 2 dots for own head only
            float kv[8];
            #pragma unroll
            for (int f = 0; f < 8; f++) {
                float4 wr = ld4(sw + O_WQKV + l*48 + (4+f)*4);
                kv[f] = fmaf(h0, wr.x, fmaf(h1, wr.y, fmaf(h2, wr.z, h3 * wr.w)));
            }
            float qa, qb;
            {
                float4 wa = ld4(sw + O_WQKV + l*48 + (2*hr)     * 4);
                float4 wb = ld4(sw + O_WQKV + l*48 + (2*hr + 1) * 4);
                qa = fmaf(h0, wa.x, fmaf(h1, wa.y, fmaf(h2, wa.z, h3 * wa.w))) * SC;
                qb = fmaf(h0, wb.x, fmaf(h1, wb.y, fmaf(h2, wb.z, h3 * wb.w))) * SC;
            }

            // publish this state's K/V, head-split: [state][head]=(k0,k1,v0,v1)
            if (r == 0) {
                *(float4*)(sw + O_SKV + (l*16 + 2*s + 0) * 4) =
                    make_float4(kv[0], kv[1], kv[4], kv[5]);   // head0
            }
            if (r == 1) {
                *(float4*)(sw + O_SKV + (l*16 + 2*s + 1) * 4) =
                    make_float4(kv[2], kv[3], kv[6], kv[7]);   // head1
            }
            __syncwarp();

            // attention, breadth-first: 8 pipelined LDS.128, 8 ex2, tree sums
            float4 c4[8];
            #pragma unroll
            for (int j = 0; j < 8; j++)
                c4[j] = ld4(sw + O_SKV + (l*16 + 2*j + hr) * 4);
            float w[8];
            #pragma unroll
            for (int j = 0; j < 8; j++)
                w[j] = cw[j] * ex2(fmaf(qa, c4[j].x, qb * c4[j].y));
            float den = ((w[0]+w[1]) + (w[2]+w[3])) + ((w[4]+w[5]) + (w[6]+w[7]));
            float a01 = fmaf(w[1], c4[1].z, w[0]*c4[0].z);
            float a23 = fmaf(w[3], c4[3].z, w[2]*c4[2].z);
            float a45 = fmaf(w[5], c4[5].z, w[4]*c4[4].z);
            float a67 = fmaf(w[7], c4[7].z, w[6]*c4[6].z);
            float aa  = (a01 + a23) + (a45 + a67);
            float b01 = fmaf(w[1], c4[1].w, w[0]*c4[0].w);
            float b23 = fmaf(w[3], c4[3].w, w[2]*c4[2].w);
            float b45 = fmaf(w[5], c4[5].w, w[4]*c4[4].w);
            float b67 = fmaf(w[7], c4[7].w, w[6]*c4[6].w);
            float ab  = (b01 + b23) + (b45 + b67);
            float inv = rcpa(den);
            float oa = aa * inv, ob = ab * inv;    // own head's output dims

            // partial Wo for own head BEFORE the recombine shfl
            float4 wo0 = ld4(sw + O_WO + l*16 + 0);
            float4 wo1 = ld4(sw + O_WO + l*16 + 4);
            float4 wo2 = ld4(sw + O_WO + l*16 + 8);
            float4 wo3 = ld4(sw + O_WO + l*16 + 12);
            float wa0 = hr ? wo0.z : wo0.x, wb0 = hr ? wo0.w : wo0.y;
            float wa1 = hr ? wo1.z : wo1.x, wb1 = hr ? wo1.w : wo1.y;
            float wa2 = hr ? wo2.z : wo2.x, wb2 = hr ? wo2.w : wo2.y;
            float wa3 = hr ? wo3.z : wo3.x, wb3 = hr ? wo3.w : wo3.y;
            float pw0 = fmaf(oa, wa0, ob * wb0);
            float pw1 = fmaf(oa, wa1, ob * wb1);
            float pw2 = fmaf(oa, wa2, ob * wb2);
            float pw3 = fmaf(oa, wa3, ob * wb3);
            float y0 = x0 + pw0 + __shfl_xor_sync(0xffffffffu, pw0, 2);
            float y1 = x1 + pw1 + __shfl_xor_sync(0xffffffffu, pw1, 2);
            float y2 = x2 + pw2 + __shfl_xor_sync(0xffffffffu, pw2, 2);
            float y3 = x3 + pw3 + __shfl_xor_sync(0xffffffffu, pw3, 2);

            // LN2 (tree-form sums)
            float4 g2 = ld4(sw + O_LN2G + l*4), b2v = ld4(sw + O_LN2B + l*4);
            mu = 0.25f * ((y0 + y1) + (y2 + y3));
            d0 = y0-mu; d1 = y1-mu; d2 = y2-mu; d3 = y3-mu;
            rr = rsqa(fmaf(0.25f, (d0*d0 + d1*d1) + (d2*d2 + d3*d3), 1e-5f));
            h0 = d0*rr*g2.x+b2v.x; h1 = d1*rr*g2.y+b2v.y;
            h2 = d2*rr*g2.z+b2v.z; h3 = d3*rr*g2.w+b2v.w;

            // FFN: role r owns hidden units 4r..4r+3 (4 branch-free gelu/lane)
            float p0 = 0.f, p1 = 0.f, p2 = 0.f, p3 = 0.f;
            #pragma unroll
            for (int j = 0; j < 4; j++) {
                int fl = r * 4 + j;
                float4 w1r = ld4(sw + O_W1 + l*64 + fl*4);
                float  bb  = sw[O_B1 + l*16 + fl];
                float ss = fmaf(h0, w1r.x, fmaf(h1, w1r.y,
                           fmaf(h2, w1r.z, fmaf(h3, w1r.w, bb))));
                float u  = 0.5f * ss * (1.0f + erf_bf(ss * 0.70710678118654752f));
                float4 w2r = ld4(sw + O_W2T + l*64 + fl*4);
                p0 = fmaf(u, w2r.x, p0); p1 = fmaf(u, w2r.y, p1);
                p2 = fmaf(u, w2r.z, p2); p3 = fmaf(u, w2r.w, p3);
            }
            #pragma unroll
            for (int m = 1; m <= 2; m <<= 1) {     // reduce over the 4 roles
                p0 += __shfl_xor_sync(0xffffffffu, p0, m);
                p1 += __shfl_xor_sync(0xffffffffu, p1, m);
                p2 += __shfl_xor_sync(0xffffffffu, p2, m);
                p3 += __shfl_xor_sync(0xffffffffu, p3, m);
            }
            float4 bf2 = ld4(sw + O_B2 + l*4);
            x0 = y0 + bf2.x + p0;
            x1 = y1 + bf2.y + p1;
            x2 = y2 + bf2.z + p2;
            x3 = y3 + bf2.w + p3;
        }

        // logits: role r computes logits 2r, 2r+1 of state s
        float4 owa = ld4(sw + O_OUTW + (2*r)     * 4);
        float4 owb = ld4(sw + O_OUTW + (2*r + 1) * 4);
        float la = fmaf(x0, owa.x, fmaf(x1, owa.y, fmaf(x2, owa.z, x3 * owa.w)));
        float lb = fmaf(x0, owb.x, fmaf(x1, owb.y, fmaf(x2, owb.z, x3 * owb.w)));
        *(float2*)(sw + O_SLOG + s * 8 + 2 * r) = make_float2(la, lb);
    } else {
        my = tp[t];                                // own 4 scatter tokens
    }

    __syncthreads();                               // the ONLY block barrier

    // ---- scatter: 4 contiguous tokens per thread (2x STG.128 each) ----
    float4* op = (float4*)(out + ((size_t)b * NS + 4 * t) * NV);
    const float4* l0 = (const float4*)(sw + O_SLOG + my.x * NV);
    const float4* l1 = (const float4*)(sw + O_SLOG + my.y * NV);
    const float4* l2 = (const float4*)(sw + O_SLOG + my.z * NV);
    const float4* l3 = (const float4*)(sw + O_SLOG + my.w * NV);
    op[0] = l0[0]; op[1] = l0[1];
    op[2] = l1[0]; op[3] = l1[1];
    op[4] = l2[0]; op[5] = l2[1];
    op[6] = l3[0]; op[7] = l3[1];
}

// ---------------------------------------------------------------------------
extern "C" void kernel_launch(void* const* d_in, const int* in_sizes, int n_in,
                              void* d_out, int out_size)
{
    const int*   tok   = (const int*)  d_in[0];
    const float* emb   = (const float*)d_in[1];
    const float* ln1_g = (const float*)d_in[2];
    const float* ln1_b = (const float*)d_in[3];
    const float* wqkv  = (const float*)d_in[4];
    const float* wo    = (const float*)d_in[5];
    const float* ln2_g = (const float*)d_in[6];
    const float* ln2_b = (const float*)d_in[7];
    const float* w1    = (const float*)d_in[8];
    const float* b1    = (const float*)d_in[9];
    const float* w2    = (const float*)d_in[10];
    const float* b2    = (const float*)d_in[11];
    const float* out_w = (const float*)d_in[12];
    float* out = (float*)d_out;

    fused_kernel<<<NB, 256>>>(tok, emb, ln1_g, ln1_b, wqkv, wo,
                              ln2_g, ln2_b, w1, b1, w2, b2, out_w, out);
}